// round 16
// baseline (speedup 1.0000x reference)
#include <cuda_runtime.h>
#include <cuda_fp16.h>
#include <math.h>
#include <stdint.h>

#define Bb 2
#define Dd 1536
#define Ss 512
#define Hh 32
#define Cc 128
#define HC 4096
#define Ff 32
#define PAIRF 128
#define P2 1024
#define TW 72   // smem tile row width (halfs); 144B row stride -> conflict-free LDSM

// ---------------- scratch (device globals) ----------------
__device__ __half g_xph[Bb*Ss*Dd];
__device__ __half g_gh [Bb*Ss*Dd];
__device__ __half g_qh [Bb*Ss*HC];
__device__ __half g_kh [Bb*Ss*HC];
__device__ __half g_posh[P2*HC];
__device__ __half g_wqt[HC*Dd];
__device__ __half g_wkt[HC*Dd];
__device__ __half g_wyqt[PAIRF*Dd];
__device__ __half g_wykt[PAIRF*Dd];
__device__ __half g_wpt[PAIRF*Hh];
__device__ __half g_ah[(size_t)Bb*Hh*Ss*Ss];
__device__ __half g_rqh[(size_t)Bb*Hh*Ss*P2];
__device__ __half g_rkh[(size_t)Bb*Hh*Ss*P2];
__device__ float g_sufq[Ff*HC];
__device__ float g_sufs[Ff*HC];
__device__ int   g_fmin[513];
__device__ float g_yq[Bb*Ss*PAIRF];
__device__ float g_yk[Bb*Ss*PAIRF];
__device__ float g_ypart[16*Bb*Ss*PAIRF];

// ---------------- helpers ----------------
__device__ __forceinline__ __half2 h2(float a, float b) {
    return __halves2half2(__float2half_rn(a), __float2half_rn(b));
}

#define MMA_F16(d, a, b) asm volatile( \
    "mma.sync.aligned.m16n8k16.row.col.f32.f16.f16.f32 " \
    "{%0,%1,%2,%3}, {%4,%5,%6,%7}, {%8,%9}, {%0,%1,%2,%3};\n" \
    : "+f"((d)[0]), "+f"((d)[1]), "+f"((d)[2]), "+f"((d)[3]) \
    : "r"((a)[0]), "r"((a)[1]), "r"((a)[2]), "r"((a)[3]), \
      "r"((b)[0]), "r"((b)[1]))

__device__ __forceinline__ void cpa16(void* dst, const void* src) {
    uint32_t d = (uint32_t)__cvta_generic_to_shared(dst);
    asm volatile("cp.async.ca.shared.global [%0], [%1], 16;\n" :: "r"(d), "l"(src));
}
#define CPCOMMIT() asm volatile("cp.async.commit_group;\n")
#define CPWAIT0()  asm volatile("cp.async.wait_group 0;\n")
#define CPWAIT1()  asm volatile("cp.async.wait_group 1;\n")

__device__ __forceinline__ uint32_t smem_u32(const void* p) {
    uint32_t a;
    asm("{ .reg .u64 t; cvta.to.shared.u64 t, %1; cvt.u32.u64 %0, t; }" : "=r"(a) : "l"(p));
    return a;
}

__device__ __forceinline__ void ldsm_x4(uint32_t* r, uint32_t addr) {
    asm volatile("ldmatrix.sync.aligned.m8n8.x4.shared.b16 {%0,%1,%2,%3}, [%4];"
        : "=r"(r[0]), "=r"(r[1]), "=r"(r[2]), "=r"(r[3]) : "r"(addr));
}

typedef __half (*Tile)[TW];

// stage a 128-row x 64-half tile into smem [128][TW]
__device__ __forceinline__ void cp_tile64(Tile dst, const __half* src, int ld, int t) {
#pragma unroll
    for (int i = 0; i < 4; ++i) {
        int c = t + 256 * i;
        int r = c >> 3, c16 = (c & 7) * 8;
        cpa16(&dst[r][c16], src + (size_t)r * ld + c16);
    }
}

// fragment compute for one 64-K stage via ldmatrix (4 k-steps of 16)
#define STAGE_MMA64_LDSM(aA, aB)                                               \
    _Pragma("unroll")                                                          \
    for (int ks = 0; ks < 4; ++ks) {                                           \
        uint32_t af[4][4], bq[2][4];                                           \
        _Pragma("unroll")                                                      \
        for (int mi = 0; mi < 4; ++mi)                                         \
            ldsm_x4(af[mi], (aA) + mi * (16 * TW * 2) + ks * 32);              \
        _Pragma("unroll")                                                      \
        for (int p = 0; p < 2; ++p)                                            \
            ldsm_x4(bq[p], (aB) + p * (16 * TW * 2) + ks * 32);                \
        _Pragma("unroll")                                                      \
        for (int mi = 0; mi < 4; ++mi) {                                       \
            _Pragma("unroll")                                                  \
            for (int p = 0; p < 2; ++p) {                                      \
                uint32_t b0[2] = {bq[p][0], bq[p][2]};                         \
                uint32_t b1[2] = {bq[p][1], bq[p][3]};                         \
                MMA_F16(acc[mi][2 * p], af[mi], b0);                           \
                MMA_F16(acc[mi][2 * p + 1], af[mi], b1);                       \
            }                                                                  \
        }                                                                      \
    }

#define TILEB (128 * TW * 2)        // 18432 bytes per tile
#define SMEMB (4 * TILEB)           // 73728 -> 2 CTAs/SM

// ---------------- init: cw/fmin (block 0) + suffix sums (blocks 1..8) ----------------
__global__ void init_kernel(const float* __restrict__ wpos) {
    int bx = blockIdx.x, t = threadIdx.x;
    if (bx == 0) {
        __shared__ float cw[32];
        if (t < 32)
            cw[t] = (float)((double)t + exp(log(481.0) * ((double)t / 32.0)));
        __syncthreads();
        if (t <= 512) {
            int fm = 32;
            for (int f = 31; f >= 0; --f)
                if (cw[f] > (float)t) fm = f;
            g_fmin[t] = fm;
        }
    } else {
        if (t < 512) {
            int hc = (bx - 1) * 512 + t;
            float aq = 0.f, as = 0.f;
            for (int f = Ff - 1; f >= 0; --f) {
                aq += wpos[f * HC + hc];
                as += wpos[(Ff + f) * HC + hc];
                g_sufq[f * HC + hc] = aq;
                g_sufs[f * HC + hc] = as;
            }
        }
    }
}

// dual fp32 [K][N] -> half [N][K] transpose (z selects pair member)
__global__ void transpose_qk2(const float* __restrict__ s0, const float* __restrict__ s1,
                              __half* __restrict__ d0, __half* __restrict__ d1,
                              int K, int N) {
    __shared__ float s[32][33];
    const float* src = blockIdx.z ? s1 : s0;
    __half* dst = blockIdx.z ? d1 : d0;
    int n0 = blockIdx.x * 32, k0 = blockIdx.y * 32;
    int tx = threadIdx.x, ty = threadIdx.y;
#pragma unroll
    for (int i = 0; i < 4; ++i)
        s[ty + 8 * i][tx] = src[(size_t)(k0 + ty + 8 * i) * N + n0 + tx];
    __syncthreads();
#pragma unroll
    for (int i = 0; i < 4; ++i)
        dst[(size_t)(n0 + ty + 8 * i) * K + k0 + tx] = __float2half_rn(s[tx][ty + 8 * i]);
}

__global__ void transpose_h(const float* __restrict__ src, __half* __restrict__ dst,
                            int K, int N) {
    __shared__ float s[32][33];
    int n0 = blockIdx.x * 32, k0 = blockIdx.y * 32;
    int tx = threadIdx.x, ty = threadIdx.y;
#pragma unroll
    for (int i = 0; i < 4; ++i)
        s[ty + 8 * i][tx] = src[(size_t)(k0 + ty + 8 * i) * N + n0 + tx];
    __syncthreads();
#pragma unroll
    for (int i = 0; i < 4; ++i)
        dst[(size_t)(n0 + ty + 8 * i) * K + k0 + tx] = __float2half_rn(s[tx][ty + 8 * i]);
}

// pool(16) + RMSNorm + gelu; one float4 per thread
__global__ void __launch_bounds__(384) pool_norm_kernel(const float* __restrict__ x,
                                                        const float* __restrict__ scale) {
    int row = blockIdx.x;
    int t = threadIdx.x;
    const float4* xr = (const float4*)(x + (size_t)row * 16 * Dd);
    float4 s = make_float4(0.f, 0.f, 0.f, 0.f);
#pragma unroll
    for (int j = 0; j < 16; ++j) {
        float4 v = xr[j * 384 + t];
        s.x += v.x; s.y += v.y; s.z += v.z; s.w += v.w;
    }
    s.x *= 0.0625f; s.y *= 0.0625f; s.z *= 0.0625f; s.w *= 0.0625f;
    float ss = s.x * s.x + s.y * s.y + s.z * s.z + s.w * s.w;
    __shared__ float red[13];
#pragma unroll
    for (int o = 16; o; o >>= 1) ss += __shfl_xor_sync(0xffffffffu, ss, o);
    if ((t & 31) == 0) red[t >> 5] = ss;
    __syncthreads();
    if (t == 0) {
        float tot = 0.f;
        for (int i = 0; i < 12; ++i) tot += red[i];
        red[12] = rsqrtf(tot * (1.f / 1536.f) + 1e-5f);
    }
    __syncthreads();
    float inv = red[12];
    float4 sc = ((const float4*)scale)[t];
    float v[4] = {s.x * inv * sc.x, s.y * inv * sc.y, s.z * inv * sc.z, s.w * inv * sc.w};
    float gl[4];
#pragma unroll
    for (int i = 0; i < 4; ++i) {
        float v3 = v[i] * v[i] * v[i];
        gl[i] = 0.5f * v[i] * (1.f + tanhf(0.7978845608028654f * (v[i] + 0.044715f * v3)));
    }
    size_t off = (size_t)row * Dd + t * 4;
    *(__half2*)&g_xph[off]     = h2(v[0], v[1]);
    *(__half2*)&g_xph[off + 2] = h2(v[2], v[3]);
    *(__half2*)&g_gh[off]      = h2(gl[0], gl[1]);
    *(__half2*)&g_gh[off + 2]  = h2(gl[2], gl[3]);
}

__global__ void __launch_bounds__(256) posenc_kernel(const float* __restrict__ bpos) {
    int p = blockIdx.x;
    int hc4 = (blockIdx.y * 256 + threadIdx.x) * 4;
    int dist = (p >= 512) ? p - 512 : 512 - p;
    int fm = g_fmin[dist];
    float4 v = *(const float4*)&bpos[hc4];
    if (fm < 32) {
        float sg = (p > 512) ? 1.f : ((p < 512) ? -1.f : 0.f);
        float4 a = *(const float4*)&g_sufq[fm * HC + hc4];
        float4 s = *(const float4*)&g_sufs[fm * HC + hc4];
        v.x += a.x + sg * s.x; v.y += a.y + sg * s.y;
        v.z += a.z + sg * s.z; v.w += a.w + sg * s.w;
    }
    __half2* dst = (__half2*)&g_posh[(size_t)p * HC + hc4];
    dst[0] = h2(v.x, v.y);
    dst[1] = h2(v.z, v.w);
}

__global__ void reduce_y_kernel() {
    int i = blockIdx.x * 256 + threadIdx.x;
    float sq = 0.f, sk = 0.f;
#pragma unroll
    for (int s = 0; s < 8; ++s) {
        sq += g_ypart[s * 131072 + i];
        sk += g_ypart[(8 + s) * 131072 + i];
    }
    g_yq[i] = sq;
    g_yk[i] = sk;
}

// ---------------- q/k projections: 2-stage pipeline (R12 exact) ----------------
__global__ void __launch_bounds__(256, 2) proj_tc() {
    extern __shared__ __half sh[];
    Tile AsT[2] = {(Tile)sh, (Tile)(sh + 128 * TW)};
    Tile BsT[2] = {(Tile)(sh + 2 * 128 * TW), (Tile)(sh + 3 * 128 * TW)};
    int sel = blockIdx.z;
    const __half* Bt = sel ? g_wkt : g_wqt;
    __half* Oq = sel ? g_kh : g_qh;
    int m0 = blockIdx.y * 128, n0 = blockIdx.x * 128;
    int t = threadIdx.x, lane = t & 31, wid = t >> 5;
    int grp = lane >> 2, tig = lane & 3;
    int moff = (wid >> 2) * 64, noff = (wid & 3) * 32;
    int lrow = lane & 15, lcol = (lane >> 4) * 8;
    uint32_t aA0 = smem_u32(&AsT[0][moff + lrow][lcol]);
    uint32_t aB0 = smem_u32(&BsT[0][noff + lrow][lcol]);
    const uint32_t bufo = TILEB;
    float acc[4][4][4] = {};
    const __half* Ab = g_xph + (size_t)m0 * Dd;
    const __half* Bp = Bt + (size_t)n0 * Dd;
    cp_tile64(AsT[0], Ab, Dd, t);
    cp_tile64(BsT[0], Bp, Dd, t);
    CPCOMMIT();
    for (int ib = 0; ib < 24; ++ib) {
        CPWAIT0();
        __syncthreads();
        if (ib < 23) {
            int st = (ib + 1) & 1, kb = (ib + 1) * 64;
            cp_tile64(AsT[st], Ab + kb, Dd, t);
            cp_tile64(BsT[st], Bp + kb, Dd, t);
            CPCOMMIT();
        }
        STAGE_MMA64_LDSM(aA0 + (ib & 1) * bufo, aB0 + (ib & 1) * bufo);
        __syncthreads();
    }
#pragma unroll
    for (int mi = 0; mi < 4; ++mi) {
        int r = m0 + moff + 16 * mi + grp;
#pragma unroll
        for (int ni = 0; ni < 4; ++ni) {
            int c = n0 + noff + 8 * ni + 2 * tig;
            *(__half2*)&Oq[(size_t)r * HC + c] = h2(acc[mi][ni][0], acc[mi][ni][1]);
            *(__half2*)&Oq[(size_t)(r + 8) * HC + c] = h2(acc[mi][ni][2], acc[mi][ni][3]);
        }
    }
}

// ---------------- y projections (k-split 192, 2-stage pipeline, R12 exact) ----------------
__global__ void __launch_bounds__(256, 2) ygemm_tc() {
    extern __shared__ __half sh[];
    Tile AsT[2] = {(Tile)sh, (Tile)(sh + 128 * TW)};
    Tile BsT[2] = {(Tile)(sh + 2 * 128 * TW), (Tile)(sh + 3 * 128 * TW)};
    int z = blockIdx.z;
    int side = z >> 3, slice = z & 7;
    const __half* Bt = side ? g_wykt : g_wyqt;
    int m0 = blockIdx.y * 128;
    int kstart = slice * 192;
    int t = threadIdx.x, lane = t & 31, wid = t >> 5;
    int grp = lane >> 2, tig = lane & 3;
    int moff = (wid >> 2) * 64, noff = (wid & 3) * 32;
    int lrow = lane & 15, lcol = (lane >> 4) * 8;
    uint32_t aA0 = smem_u32(&AsT[0][moff + lrow][lcol]);
    uint32_t aB0 = smem_u32(&BsT[0][noff + lrow][lcol]);
    const uint32_t bufo = TILEB;
    float acc[4][4][4] = {};
    const __half* Ab = g_gh + (size_t)m0 * Dd + kstart;
    const __half* Bp = Bt + kstart;
    cp_tile64(AsT[0], Ab, Dd, t);
    cp_tile64(BsT[0], Bp, Dd, t);
    CPCOMMIT();
    for (int ib = 0; ib < 3; ++ib) {
        CPWAIT0();
        __syncthreads();
        if (ib < 2) {
            int st = (ib + 1) & 1, kb = (ib + 1) * 64;
            cp_tile64(AsT[st], Ab + kb, Dd, t);
            cp_tile64(BsT[st], Bp + kb, Dd, t);
            CPCOMMIT();
        }
        STAGE_MMA64_LDSM(aA0 + (ib & 1) * bufo, aB0 + (ib & 1) * bufo);
        __syncthreads();
    }
    float* Cp = g_ypart + (size_t)z * 131072;
#pragma unroll
    for (int mi = 0; mi < 4; ++mi) {
        int r = m0 + moff + 16 * mi + grp;
#pragma unroll
        for (int ni = 0; ni < 4; ++ni) {
            int c = noff + 8 * ni + 2 * tig;
            *(float2*)&Cp[(size_t)r * 128 + c] = make_float2(acc[mi][ni][0], acc[mi][ni][1]);
            *(float2*)&Cp[(size_t)(r + 8) * 128 + c] = make_float2(acc[mi][ni][2], acc[mi][ni][3]);
        }
    }
}

// ---------------- BANDED rel logits: one block = q-tile x full 5-tile band ----------------
// grid (4, 128): x = q-tile (my), y = z (side*64 + bh)
// smem: A0 (k0-63), A1 (k64-127) resident; B double-buffered one 64-K tile at a time.
__global__ void __launch_bounds__(256, 2) rel_band(const float* __restrict__ qrb,
                                                   const float* __restrict__ krb) {
    extern __shared__ __half sh[];
    __shared__ float rbs[128];
    __shared__ float rds[128];
    int z = blockIdx.y;
    int side = z >> 6, bh = z & 63, b = bh >> 5, h = bh & 31;
    const __half* A  = (side ? g_kh : g_qh) + (size_t)b * Ss * HC + h * Cc;
    const __half* Bt = g_posh + h * Cc;
    __half* Cp = (side ? g_rkh : g_rqh) + (size_t)bh * (Ss * P2);
    const float* rb = (side ? krb : qrb) + h * Cc;
    int my = blockIdx.x;
    int m0 = my * 128;
    int t = threadIdx.x, lane = t & 31, wid = t >> 5;
    int grp = lane >> 2, tig = lane & 3;
    int moff = (wid >> 2) * 64, noff = (wid & 3) * 32;
    int lrow = lane & 15, lcol = (lane >> 4) * 8;
    Tile A0 = (Tile)sh, A1 = (Tile)(sh + 128 * TW);
    Tile Bf[2] = {(Tile)(sh + 2 * 128 * TW), (Tile)(sh + 3 * 128 * TW)};
    uint32_t aA = smem_u32(&A0[moff + lrow][lcol]);
    uint32_t aB = smem_u32(&Bf[0][noff + lrow][lcol]);
    const uint32_t bufo = TILEB;
    if (t < 128) rbs[t] = rb[t];
    const __half* Ab = A + (size_t)m0 * HC;
    // prologue: A both chunks + B stage 0
    cp_tile64(A0, Ab, HC, t);
    cp_tile64(A1, Ab + 64, HC, t);
    cp_tile64(Bf[0], Bt + (size_t)((3 - my) * 128) * HC, HC, t);
    CPCOMMIT();
    float acc[4][4][4] = {};
    float dotacc = 0.f;
    for (int s = 0; s < 10; ++s) {
        int nt = s >> 1, kc = s & 1;
        int n0 = (nt + 3 - my) * 128;
        CPWAIT0();
        __syncthreads();
        if (s < 9) {
            int sn = s + 1;
            int n0n = ((sn >> 1) + 3 - my) * 128;
            cp_tile64(Bf[sn & 1], Bt + (size_t)n0n * HC + (sn & 1) * 64, HC, t);
            CPCOMMIT();
        }
        STAGE_MMA64_LDSM(aA + kc * bufo, aB + (s & 1) * bufo);
        // bias-dot partial over this 64-K chunk of the current B tile
        if (t < 128) {
            Tile Bc = Bf[s & 1];
            float ds = 0.f;
#pragma unroll 16
            for (int k = 0; k < 64; ++k)
                ds += rbs[kc * 64 + k] * __half2float(Bc[t][k]);
            dotacc += ds;
        }
        if (kc == 1) {
            if (t < 128) { rds[t] = dotacc; dotacc = 0.f; }
            __syncthreads();
#pragma unroll
            for (int mi = 0; mi < 4; ++mi) {
                int r = m0 + moff + 16 * mi + grp;
#pragma unroll
                for (int ni = 0; ni < 4; ++ni) {
                    int cl = noff + 8 * ni + 2 * tig;
                    int c = n0 + cl;
                    float r0 = rds[cl], r1 = rds[cl + 1];
                    *(__half2*)&Cp[(size_t)r * P2 + c] =
                        h2(acc[mi][ni][0] + r0, acc[mi][ni][1] + r1);
                    *(__half2*)&Cp[(size_t)(r + 8) * P2 + c] =
                        h2(acc[mi][ni][2] + r0, acc[mi][ni][3] + r1);
#pragma unroll
                    for (int q = 0; q < 4; ++q) acc[mi][ni][q] = 0.f;
                }
            }
        }
    }
}

// ---------------- a = QK^T + 0.5*(rq + rk gathers), writes half (R12 exact) ----------------
__global__ void __launch_bounds__(256, 2) a_tc() {
    extern __shared__ __half sh[];
    int bh = blockIdx.z, b = bh >> 5, h = bh & 31;
    const __half* A  = g_qh + (size_t)b * Ss * HC + h * Cc;
    const __half* Bt = g_kh + (size_t)b * Ss * HC + h * Cc;
    const __half* rqb = g_rqh + (size_t)bh * (Ss * P2);
    const __half* rkb = g_rkh + (size_t)bh * (Ss * P2);
    __half* Cp = g_ah + (size_t)bh * (Ss * Ss);
    int m0 = blockIdx.y * 128, n0 = blockIdx.x * 128;
    int t = threadIdx.x, lane = t & 31, wid = t >> 5;
    int grp = lane >> 2, tig = lane & 3;
    int moff = (wid >> 2) * 64, noff = (wid & 3) * 32;
    int lrow = lane & 15, lcol = (lane >> 4) * 8;
    uint32_t aA0 = smem_u32(&((Tile)sh)[moff + lrow][lcol]);
    uint32_t aB0 = smem_u32(&((Tile)(sh + 2 * 128 * TW))[noff + lrow][lcol]);
    const uint32_t bufo = TILEB;
    float acc[4][4][4] = {};
    const __half* Ab = A + (size_t)m0 * HC;
    const __half* Bp = Bt + (size_t)n0 * HC;
    Tile AsT0 = (Tile)sh, AsT1 = (Tile)(sh + 128 * TW);
    Tile BsT0 = (Tile)(sh + 2 * 128 * TW), BsT1 = (Tile)(sh + 3 * 128 * TW);
    cp_tile64(AsT0, Ab, HC, t);
    cp_tile64(BsT0, Bp, HC, t);
    CPCOMMIT();
    cp_tile64(AsT1, Ab + 64, HC, t);
    cp_tile64(BsT1, Bp + 64, HC, t);
    CPCOMMIT();
    CPWAIT1();
    __syncthreads();
    STAGE_MMA64_LDSM(aA0, aB0);
    CPWAIT0();
    __syncthreads();
    STAGE_MMA64_LDSM(aA0 + bufo, aB0 + bufo);
#pragma unroll
    for (int mi = 0; mi < 4; ++mi) {
        int q0 = m0 + moff + 16 * mi + grp;
#pragma unroll
        for (int ni = 0; ni < 4; ++ni) {
            int kg = n0 + noff + 8 * ni + 2 * tig;
            float rq00 = __half2float(rqb[(size_t)q0 * P2 + kg - q0 + 512]);
            float rq01 = __half2float(rqb[(size_t)q0 * P2 + kg + 1 - q0 + 512]);
            float rq10 = __half2float(rqb[(size_t)(q0 + 8) * P2 + kg - q0 - 8 + 512]);
            float rq11 = __half2float(rqb[(size_t)(q0 + 8) * P2 + kg + 1 - q0 - 8 + 512]);
            float rk00 = __half2float(rkb[(size_t)kg * P2 + q0 - kg + 512]);
            float rk01 = __half2float(rkb[(size_t)(kg + 1) * P2 + q0 - kg - 1 + 512]);
            float rk10 = __half2float(rkb[(size_t)kg * P2 + q0 + 8 - kg + 512]);
            float rk11 = __half2float(rkb[(size_t)(kg + 1) * P2 + q0 + 7 - kg + 512]);
            *(__half2*)&Cp[(size_t)q0 * Ss + kg] =
                h2(acc[mi][ni][0] + 0.5f * (rq00 + rk00),
                   acc[mi][ni][1] + 0.5f * (rq01 + rk01));
            *(__half2*)&Cp[(size_t)(q0 + 8) * Ss + kg] =
                h2(acc[mi][ni][2] + 0.5f * (rq10 + rk10),
                   acc[mi][ni][3] + 0.5f * (rq11 + rk11));
        }
    }
}

// ---------------- final v2: block = (k-tile, q-chunk of 16, b)  (R12 exact) ----------------
__global__ void __launch_bounds__(256) final_tc2(const float* __restrict__ bpair,
                                                 float* __restrict__ out) {
    __shared__ __half At_s[2][128][34];
    __shared__ __half Ws[128][40];
    __shared__ float basef[2][128];
    int k0 = blockIdx.x * 128;
    int q0c = blockIdx.y * 16;
    int b = blockIdx.z;
    int t = threadIdx.x, lane = t & 31, wid = t >> 5;
    int grp = lane >> 2, tig = lane & 3;
    int moff = (wid >> 2) * 64, noff = (wid & 3) * 32;
#pragma unroll
    for (int i = 0; i < 2; ++i) {
        int c = t + 256 * i;
        int r = c >> 2, c16 = (c & 3) * 8;
        cpa16(&Ws[r][c16], g_wpt + (size_t)r * 32 + c16);
    }
    CPCOMMIT();
    float bpr = (t < 128) ? bpair[t] : 0.f;
    float2 ykr[4][4][2];
#pragma unroll
    for (int mi = 0; mi < 4; ++mi) {
        int kl0 = moff + 16 * mi + grp;
#pragma unroll
        for (int ni = 0; ni < 4; ++ni) {
            int f = noff + 8 * ni + 2 * tig;
            ykr[mi][ni][0] = *(const float2*)&g_yk[((size_t)(b * 512 + k0 + kl0)) * 128 + f];
            ykr[mi][ni][1] = *(const float2*)&g_yk[((size_t)(b * 512 + k0 + kl0 + 8)) * 128 + f];
        }
    }
    if (t < 128) basef[0][t] = bpr + g_yq[((size_t)(b * 512 + q0c)) * 128 + t];
#pragma unroll
    for (int it = 0; it < 8; ++it) {
        int id = t + 256 * it;
        int hh = id >> 6, j = id & 63;
        __half2 v = *(const __half2*)&g_ah[(((size_t)(b * 32 + hh) * Ss + q0c) * Ss) + k0 + 2 * j];
        At_s[0][2 * j][hh] = __low2half(v);
        At_s[0][2 * j + 1][hh] = __high2half(v);
    }
    CPWAIT0();
    for (int qi = 0; qi < 16; ++qi) {
        int cur = qi & 1, nxt = cur ^ 1;
        __syncthreads();
        if (qi < 15) {
            int qn = q0c + qi + 1;
            if (t < 128) basef[nxt][t] = bpr + g_yq[((size_t)(b * 512 + qn)) * 128 + t];
#pragma unroll
            for (int it = 0; it < 8; ++it) {
                int id = t + 256 * it;
                int hh = id >> 6, j = id & 63;
                __half2 v = *(const __half2*)&g_ah[(((size_t)(b * 32 + hh) * Ss + qn) * Ss) + k0 + 2 * j];
                At_s[nxt][2 * j][hh] = __low2half(v);
                At_s[nxt][2 * j + 1][hh] = __high2half(v);
            }
        }
        float acc[4][4][4] = {};
#pragma unroll
        for (int ks = 0; ks < 2; ++ks) {
            int koff = ks * 16 + 2 * tig;
            uint32_t af[4][4], bf[4][2];
#pragma unroll
            for (int mi = 0; mi < 4; ++mi) {
                int r = moff + 16 * mi + grp;
                af[mi][0] = *(const uint32_t*)&At_s[cur][r][koff];
                af[mi][1] = *(const uint32_t*)&At_s[cur][r + 8][koff];
                af[mi][2] = *(const uint32_t*)&At_s[cur][r][koff + 8];
                af[mi][3] = *(const uint32_t*)&At_s[cur][r + 8][koff + 8];
            }
#pragma unroll
            for (int ni = 0; ni < 4; ++ni) {
                int c = noff + 8 * ni + grp;
                bf[ni][0] = *(const uint32_t*)&Ws[c][koff];
                bf[ni][1] = *(const uint32_t*)&Ws[c][koff + 8];
            }
#pragma unroll
            for (int mi = 0; mi < 4; ++mi)
#pragma unroll
                for (int ni = 0; ni < 4; ++ni) MMA_F16(acc[mi][ni], af[mi], bf[ni]);
        }
        int q = q0c + qi;
        size_t rb = ((size_t)(b * 512 + q) * 512 + k0);
#pragma unroll
        for (int mi = 0; mi < 4; ++mi) {
            int kl0 = moff + 16 * mi + grp;
            size_t row0 = (rb + kl0) * 128, row1 = row0 + (size_t)8 * 128;
#pragma unroll
            for (int ni = 0; ni < 4; ++ni) {
                int f = noff + 8 * ni + 2 * tig;
                float b0 = basef[cur][f], b1 = basef[cur][f + 1];
                *(float2*)&out[row0 + f] = make_float2(acc[mi][ni][0] + b0 + ykr[mi][ni][0].x,
                                                       acc[mi][ni][1] + b1 + ykr[mi][ni][0].y);
                *(float2*)&out[row1 + f] = make_float2(acc[mi][ni][2] + b0 + ykr[mi][ni][1].x,
                                                       acc[mi][ni][3] + b1 + ykr[mi][ni][1].y);
            }
        }
    }
}

// ---------------- launcher (R12 schedule + banded rel) ----------------
extern "C" void kernel_launch(void* const* d_in, const int* in_sizes, int n_in,
                              void* d_out, int out_size) {
    const float* x        = (const float*)d_in[0];
    const float* scale    = (const float*)d_in[1];
    const float* w_q      = (const float*)d_in[2];
    const float* w_k      = (const float*)d_in[3];
    const float* w_pos    = (const float*)d_in[4];
    const float* b_pos    = (const float*)d_in[5];
    const float* q_r_bias = (const float*)d_in[6];
    const float* k_r_bias = (const float*)d_in[7];
    const float* w_yq     = (const float*)d_in[8];
    const float* w_yk     = (const float*)d_in[9];
    const float* w_pair   = (const float*)d_in[10];
    const float* b_pair   = (const float*)d_in[11];
    float* out = (float*)d_out;

    __half *p_wqt, *p_wkt, *p_wyqt, *p_wykt, *p_wpt;
    cudaGetSymbolAddress((void**)&p_wqt, g_wqt);
    cudaGetSymbolAddress((void**)&p_wkt, g_wkt);
    cudaGetSymbolAddress((void**)&p_wyqt, g_wyqt);
    cudaGetSymbolAddress((void**)&p_wykt, g_wykt);
    cudaGetSymbolAddress((void**)&p_wpt, g_wpt);

    cudaFuncSetAttribute(proj_tc, cudaFuncAttributeMaxDynamicSharedMemorySize, SMEMB);
    cudaFuncSetAttribute(ygemm_tc, cudaFuncAttributeMaxDynamicSharedMemorySize, SMEMB);
    cudaFuncSetAttribute(rel_band, cudaFuncAttributeMaxDynamicSharedMemorySize, SMEMB);
    cudaFuncSetAttribute(a_tc, cudaFuncAttributeMaxDynamicSharedMemorySize, SMEMB);

    transpose_qk2<<<dim3(128, 48, 2), dim3(32, 8)>>>(w_q, w_k, p_wqt, p_wkt, Dd, HC); // 1
    pool_norm_kernel<<<1024, 384>>>(x, scale);                                        // 2
    init_kernel<<<9, 544>>>(w_pos);                                                   // 3
    proj_tc<<<dim3(32, 8, 2), 256, SMEMB>>>();                                        // 4
    posenc_kernel<<<dim3(1024, 4), 256>>>(b_pos);                                     // 5
    transpose_qk2<<<dim3(4, 48, 2), dim3(32, 8)>>>(w_yq, w_yk, p_wyqt, p_wykt, Dd, PAIRF); // 6
    transpose_h<<<dim3(4, 1), dim3(32, 8)>>>(w_pair, p_wpt, Hh, PAIRF);               // 7
    ygemm_tc<<<dim3(1, 8, 16), 256, SMEMB>>>();                                       // 8
    reduce_y_kernel<<<512, 256>>>();                                                  // 9
    rel_band<<<dim3(4, 128), 256, SMEMB>>>(q_r_bias, k_r_bias);                       // 10
    a_tc<<<dim3(4, 4, 64), 256, SMEMB>>>();                                           // 11
    final_tc2<<<dim3(4, 32, 2), 256>>>(b_pair, out);                                  // 12
}

// round 17
// speedup vs baseline: 1.0611x; 1.0611x over previous
#include <cuda_runtime.h>
#include <cuda_fp16.h>
#include <math.h>
#include <stdint.h>

#define Bb 2
#define Dd 1536
#define Ss 512
#define Hh 32
#define Cc 128
#define HC 4096
#define Ff 32
#define PAIRF 128
#define P2 1024
#define TW 72   // smem tile row width (halfs); 144B row stride -> conflict-free LDSM

// ---------------- scratch (device globals) ----------------
__device__ __half g_xph[Bb*Ss*Dd];
__device__ __half g_gh [Bb*Ss*Dd];
__device__ __half g_qh [Bb*Ss*HC];
__device__ __half g_kh [Bb*Ss*HC];
__device__ __half g_posh[P2*HC];
__device__ __half g_wqt[HC*Dd];
__device__ __half g_wkt[HC*Dd];
__device__ __half g_wyqt[PAIRF*Dd];
__device__ __half g_wykt[PAIRF*Dd];
__device__ __half g_wpt[PAIRF*Hh];
__device__ __half g_ah[(size_t)Bb*Hh*Ss*Ss];
__device__ __half g_rqh[(size_t)Bb*Hh*Ss*P2];
__device__ __half g_rkh[(size_t)Bb*Hh*Ss*P2];
__device__ float g_sufq[Ff*HC];
__device__ float g_sufs[Ff*HC];
__device__ int   g_fmin[513];
__device__ float g_yq[Bb*Ss*PAIRF];
__device__ float g_yk[Bb*Ss*PAIRF];
__device__ float g_ypart[16*Bb*Ss*PAIRF];

// ---------------- helpers ----------------
__device__ __forceinline__ __half2 h2(float a, float b) {
    return __halves2half2(__float2half_rn(a), __float2half_rn(b));
}

#define MMA_F16(d, a, b) asm volatile( \
    "mma.sync.aligned.m16n8k16.row.col.f32.f16.f16.f32 " \
    "{%0,%1,%2,%3}, {%4,%5,%6,%7}, {%8,%9}, {%0,%1,%2,%3};\n" \
    : "+f"((d)[0]), "+f"((d)[1]), "+f"((d)[2]), "+f"((d)[3]) \
    : "r"((a)[0]), "r"((a)[1]), "r"((a)[2]), "r"((a)[3]), \
      "r"((b)[0]), "r"((b)[1]))

__device__ __forceinline__ void cpa16(void* dst, const void* src) {
    uint32_t d = (uint32_t)__cvta_generic_to_shared(dst);
    asm volatile("cp.async.ca.shared.global [%0], [%1], 16;\n" :: "r"(d), "l"(src));
}
#define CPCOMMIT() asm volatile("cp.async.commit_group;\n")
#define CPWAIT0()  asm volatile("cp.async.wait_group 0;\n")
#define CPWAIT1()  asm volatile("cp.async.wait_group 1;\n")

__device__ __forceinline__ uint32_t smem_u32(const void* p) {
    uint32_t a;
    asm("{ .reg .u64 t; cvta.to.shared.u64 t, %1; cvt.u32.u64 %0, t; }" : "=r"(a) : "l"(p));
    return a;
}

__device__ __forceinline__ void ldsm_x4(uint32_t* r, uint32_t addr) {
    asm volatile("ldmatrix.sync.aligned.m8n8.x4.shared.b16 {%0,%1,%2,%3}, [%4];"
        : "=r"(r[0]), "=r"(r[1]), "=r"(r[2]), "=r"(r[3]) : "r"(addr));
}

typedef __half (*Tile)[TW];

// stage a 128-row x 64-half tile into smem [128][TW]
__device__ __forceinline__ void cp_tile64(Tile dst, const __half* src, int ld, int t) {
#pragma unroll
    for (int i = 0; i < 4; ++i) {
        int c = t + 256 * i;
        int r = c >> 3, c16 = (c & 7) * 8;
        cpa16(&dst[r][c16], src + (size_t)r * ld + c16);
    }
}

// fragment compute for one 64-K stage via ldmatrix (4 k-steps of 16)
#define STAGE_MMA64_LDSM(aA, aB)                                               \
    _Pragma("unroll")                                                          \
    for (int ks = 0; ks < 4; ++ks) {                                           \
        uint32_t af[4][4], bq[2][4];                                           \
        _Pragma("unroll")                                                      \
        for (int mi = 0; mi < 4; ++mi)                                         \
            ldsm_x4(af[mi], (aA) + mi * (16 * TW * 2) + ks * 32);              \
        _Pragma("unroll")                                                      \
        for (int p = 0; p < 2; ++p)                                            \
            ldsm_x4(bq[p], (aB) + p * (16 * TW * 2) + ks * 32);                \
        _Pragma("unroll")                                                      \
        for (int mi = 0; mi < 4; ++mi) {                                       \
            _Pragma("unroll")                                                  \
            for (int p = 0; p < 2; ++p) {                                      \
                uint32_t b0[2] = {bq[p][0], bq[p][2]};                         \
                uint32_t b1[2] = {bq[p][1], bq[p][3]};                         \
                MMA_F16(acc[mi][2 * p], af[mi], b0);                           \
                MMA_F16(acc[mi][2 * p + 1], af[mi], b1);                       \
            }                                                                  \
        }                                                                      \
    }

#define TILEB (128 * TW * 2)        // 18432 bytes per tile
#define SMEMB (4 * TILEB)           // 2-stage (A,B)x2 = 73728 -> 2 CTAs/SM

// ---------------- init: cw/fmin (block 0) + suffix sums (blocks 1..8) ----------------
__global__ void init_kernel(const float* __restrict__ wpos) {
    int bx = blockIdx.x, t = threadIdx.x;
    if (bx == 0) {
        __shared__ float cw[32];
        if (t < 32)
            cw[t] = (float)((double)t + exp(log(481.0) * ((double)t / 32.0)));
        __syncthreads();
        if (t <= 512) {
            int fm = 32;
            for (int f = 31; f >= 0; --f)
                if (cw[f] > (float)t) fm = f;
            g_fmin[t] = fm;
        }
    } else {
        if (t < 512) {
            int hc = (bx - 1) * 512 + t;
            float aq = 0.f, as = 0.f;
            for (int f = Ff - 1; f >= 0; --f) {
                aq += wpos[f * HC + hc];
                as += wpos[(Ff + f) * HC + hc];
                g_sufq[f * HC + hc] = aq;
                g_sufs[f * HC + hc] = as;
            }
        }
    }
}

// dual fp32 [K][N] -> half [N][K] transpose (z selects pair member)
__global__ void transpose_qk2(const float* __restrict__ s0, const float* __restrict__ s1,
                              __half* __restrict__ d0, __half* __restrict__ d1,
                              int K, int N) {
    __shared__ float s[32][33];
    const float* src = blockIdx.z ? s1 : s0;
    __half* dst = blockIdx.z ? d1 : d0;
    int n0 = blockIdx.x * 32, k0 = blockIdx.y * 32;
    int tx = threadIdx.x, ty = threadIdx.y;
#pragma unroll
    for (int i = 0; i < 4; ++i)
        s[ty + 8 * i][tx] = src[(size_t)(k0 + ty + 8 * i) * N + n0 + tx];
    __syncthreads();
#pragma unroll
    for (int i = 0; i < 4; ++i)
        dst[(size_t)(n0 + ty + 8 * i) * K + k0 + tx] = __float2half_rn(s[tx][ty + 8 * i]);
}

__global__ void transpose_h(const float* __restrict__ src, __half* __restrict__ dst,
                            int K, int N) {
    __shared__ float s[32][33];
    int n0 = blockIdx.x * 32, k0 = blockIdx.y * 32;
    int tx = threadIdx.x, ty = threadIdx.y;
#pragma unroll
    for (int i = 0; i < 4; ++i)
        s[ty + 8 * i][tx] = src[(size_t)(k0 + ty + 8 * i) * N + n0 + tx];
    __syncthreads();
#pragma unroll
    for (int i = 0; i < 4; ++i)
        dst[(size_t)(n0 + ty + 8 * i) * K + k0 + tx] = __float2half_rn(s[tx][ty + 8 * i]);
}

// pool(16) + RMSNorm + gelu; one float4 per thread
__global__ void __launch_bounds__(384) pool_norm_kernel(const float* __restrict__ x,
                                                        const float* __restrict__ scale) {
    int row = blockIdx.x;
    int t = threadIdx.x;
    const float4* xr = (const float4*)(x + (size_t)row * 16 * Dd);
    float4 s = make_float4(0.f, 0.f, 0.f, 0.f);
#pragma unroll
    for (int j = 0; j < 16; ++j) {
        float4 v = xr[j * 384 + t];
        s.x += v.x; s.y += v.y; s.z += v.z; s.w += v.w;
    }
    s.x *= 0.0625f; s.y *= 0.0625f; s.z *= 0.0625f; s.w *= 0.0625f;
    float ss = s.x * s.x + s.y * s.y + s.z * s.z + s.w * s.w;
    __shared__ float red[13];
#pragma unroll
    for (int o = 16; o; o >>= 1) ss += __shfl_xor_sync(0xffffffffu, ss, o);
    if ((t & 31) == 0) red[t >> 5] = ss;
    __syncthreads();
    if (t == 0) {
        float tot = 0.f;
        for (int i = 0; i < 12; ++i) tot += red[i];
        red[12] = rsqrtf(tot * (1.f / 1536.f) + 1e-5f);
    }
    __syncthreads();
    float inv = red[12];
    float4 sc = ((const float4*)scale)[t];
    float v[4] = {s.x * inv * sc.x, s.y * inv * sc.y, s.z * inv * sc.z, s.w * inv * sc.w};
    float gl[4];
#pragma unroll
    for (int i = 0; i < 4; ++i) {
        float v3 = v[i] * v[i] * v[i];
        gl[i] = 0.5f * v[i] * (1.f + tanhf(0.7978845608028654f * (v[i] + 0.044715f * v3)));
    }
    size_t off = (size_t)row * Dd + t * 4;
    *(__half2*)&g_xph[off]     = h2(v[0], v[1]);
    *(__half2*)&g_xph[off + 2] = h2(v[2], v[3]);
    *(__half2*)&g_gh[off]      = h2(gl[0], gl[1]);
    *(__half2*)&g_gh[off + 2]  = h2(gl[2], gl[3]);
}

__global__ void __launch_bounds__(256) posenc_kernel(const float* __restrict__ bpos) {
    int p = blockIdx.x;
    int hc4 = (blockIdx.y * 256 + threadIdx.x) * 4;
    int dist = (p >= 512) ? p - 512 : 512 - p;
    int fm = g_fmin[dist];
    float4 v = *(const float4*)&bpos[hc4];
    if (fm < 32) {
        float sg = (p > 512) ? 1.f : ((p < 512) ? -1.f : 0.f);
        float4 a = *(const float4*)&g_sufq[fm * HC + hc4];
        float4 s = *(const float4*)&g_sufs[fm * HC + hc4];
        v.x += a.x + sg * s.x; v.y += a.y + sg * s.y;
        v.z += a.z + sg * s.z; v.w += a.w + sg * s.w;
    }
    __half2* dst = (__half2*)&g_posh[(size_t)p * HC + hc4];
    dst[0] = h2(v.x, v.y);
    dst[1] = h2(v.z, v.w);
}

__global__ void reduce_y_kernel() {
    int i = blockIdx.x * 256 + threadIdx.x;
    float sq = 0.f, sk = 0.f;
#pragma unroll
    for (int s = 0; s < 8; ++s) {
        sq += g_ypart[s * 131072 + i];
        sk += g_ypart[(8 + s) * 131072 + i];
    }
    g_yq[i] = sq;
    g_yk[i] = sk;
}

// ---------------- q/k projections: 2-stage pipeline, ONE barrier per stage ----------------
__global__ void __launch_bounds__(256, 2) proj_tc() {
    extern __shared__ __half sh[];
    Tile AsT[2] = {(Tile)sh, (Tile)(sh + 128 * TW)};
    Tile BsT[2] = {(Tile)(sh + 2 * 128 * TW), (Tile)(sh + 3 * 128 * TW)};
    int sel = blockIdx.z;
    const __half* Bt = sel ? g_wkt : g_wqt;
    __half* Oq = sel ? g_kh : g_qh;
    int m0 = blockIdx.y * 128, n0 = blockIdx.x * 128;
    int t = threadIdx.x, lane = t & 31, wid = t >> 5;
    int grp = lane >> 2, tig = lane & 3;
    int moff = (wid >> 2) * 64, noff = (wid & 3) * 32;
    int lrow = lane & 15, lcol = (lane >> 4) * 8;
    uint32_t aA0 = smem_u32(&AsT[0][moff + lrow][lcol]);
    uint32_t aB0 = smem_u32(&BsT[0][noff + lrow][lcol]);
    const uint32_t bufo = TILEB;
    float acc[4][4][4] = {};
    const __half* Ab = g_xph + (size_t)m0 * Dd;
    const __half* Bp = Bt + (size_t)n0 * Dd;
    cp_tile64(AsT[0], Ab, Dd, t);
    cp_tile64(BsT[0], Bp, Dd, t);
    CPCOMMIT();
    for (int ib = 0; ib < 24; ++ib) {
        CPWAIT0();
        __syncthreads();   // single barrier per stage (buffer-reuse safety: see R13 analysis)
        if (ib < 23) {
            int st = (ib + 1) & 1, kb = (ib + 1) * 64;
            cp_tile64(AsT[st], Ab + kb, Dd, t);
            cp_tile64(BsT[st], Bp + kb, Dd, t);
            CPCOMMIT();
        }
        STAGE_MMA64_LDSM(aA0 + (ib & 1) * bufo, aB0 + (ib & 1) * bufo);
    }
#pragma unroll
    for (int mi = 0; mi < 4; ++mi) {
        int r = m0 + moff + 16 * mi + grp;
#pragma unroll
        for (int ni = 0; ni < 4; ++ni) {
            int c = n0 + noff + 8 * ni + 2 * tig;
            *(__half2*)&Oq[(size_t)r * HC + c] = h2(acc[mi][ni][0], acc[mi][ni][1]);
            *(__half2*)&Oq[(size_t)(r + 8) * HC + c] = h2(acc[mi][ni][2], acc[mi][ni][3]);
        }
    }
}

// ---------------- y projections (k-split 192, ONE barrier per stage) ----------------
__global__ void __launch_bounds__(256, 2) ygemm_tc() {
    extern __shared__ __half sh[];
    Tile AsT[2] = {(Tile)sh, (Tile)(sh + 128 * TW)};
    Tile BsT[2] = {(Tile)(sh + 2 * 128 * TW), (Tile)(sh + 3 * 128 * TW)};
    int z = blockIdx.z;
    int side = z >> 3, slice = z & 7;
    const __half* Bt = side ? g_wykt : g_wyqt;
    int m0 = blockIdx.y * 128;
    int kstart = slice * 192;
    int t = threadIdx.x, lane = t & 31, wid = t >> 5;
    int grp = lane >> 2, tig = lane & 3;
    int moff = (wid >> 2) * 64, noff = (wid & 3) * 32;
    int lrow = lane & 15, lcol = (lane >> 4) * 8;
    uint32_t aA0 = smem_u32(&AsT[0][moff + lrow][lcol]);
    uint32_t aB0 = smem_u32(&BsT[0][noff + lrow][lcol]);
    const uint32_t bufo = TILEB;
    float acc[4][4][4] = {};
    const __half* Ab = g_gh + (size_t)m0 * Dd + kstart;
    const __half* Bp = Bt + kstart;
    cp_tile64(AsT[0], Ab, Dd, t);
    cp_tile64(BsT[0], Bp, Dd, t);
    CPCOMMIT();
    for (int ib = 0; ib < 3; ++ib) {
        CPWAIT0();
        __syncthreads();
        if (ib < 2) {
            int st = (ib + 1) & 1, kb = (ib + 1) * 64;
            cp_tile64(AsT[st], Ab + kb, Dd, t);
            cp_tile64(BsT[st], Bp + kb, Dd, t);
            CPCOMMIT();
        }
        STAGE_MMA64_LDSM(aA0 + (ib & 1) * bufo, aB0 + (ib & 1) * bufo);
    }
    float* Cp = g_ypart + (size_t)z * 131072;
#pragma unroll
    for (int mi = 0; mi < 4; ++mi) {
        int r = m0 + moff + 16 * mi + grp;
#pragma unroll
        for (int ni = 0; ni < 4; ++ni) {
            int c = noff + 8 * ni + 2 * tig;
            *(float2*)&Cp[(size_t)r * 128 + c] = make_float2(acc[mi][ni][0], acc[mi][ni][1]);
            *(float2*)&Cp[(size_t)(r + 8) * 128 + c] = make_float2(acc[mi][ni][2], acc[mi][ni][3]);
        }
    }
}

// ---------------- rel logits (NT, band-restricted; bias dot in-kernel)  (R12 exact) ----------------
__global__ void __launch_bounds__(256, 2) rel_tc(const float* __restrict__ qrb,
                                                 const float* __restrict__ krb) {
    extern __shared__ __half sh[];
    __shared__ float rbs[128];
    __shared__ float rds[128];
    int z = blockIdx.z;
    int side = z >> 6, bh = z & 63, b = bh >> 5, h = bh & 31;
    const __half* A  = (side ? g_kh : g_qh) + (size_t)b * Ss * HC + h * Cc;
    const __half* Bt = g_posh + h * Cc;
    __half* Cp = (side ? g_rkh : g_rqh) + (size_t)bh * (Ss * P2);
    const float* rb = (side ? krb : qrb) + h * Cc;
    int my = blockIdx.y;
    int m0 = my * 128;
    int n0 = (blockIdx.x + 3 - my) * 128;
    int t = threadIdx.x, lane = t & 31, wid = t >> 5;
    int grp = lane >> 2, tig = lane & 3;
    int moff = (wid >> 2) * 64, noff = (wid & 3) * 32;
    int lrow = lane & 15, lcol = (lane >> 4) * 8;
    uint32_t aA0 = smem_u32(&((Tile)sh)[moff + lrow][lcol]);
    uint32_t aB0 = smem_u32(&((Tile)(sh + 2 * 128 * TW))[noff + lrow][lcol]);
    const uint32_t bufo = TILEB;
    float acc[4][4][4] = {};
    const __half* Ab = A + (size_t)m0 * HC;
    const __half* Bp = Bt + (size_t)n0 * HC;
    Tile AsT0 = (Tile)sh, AsT1 = (Tile)(sh + 128 * TW);
    Tile BsT0 = (Tile)(sh + 2 * 128 * TW), BsT1 = (Tile)(sh + 3 * 128 * TW);
    if (t < 128) rbs[t] = rb[t];
    cp_tile64(AsT0, Ab, HC, t);
    cp_tile64(BsT0, Bp, HC, t);
    CPCOMMIT();
    cp_tile64(AsT1, Ab + 64, HC, t);
    cp_tile64(BsT1, Bp + 64, HC, t);
    CPCOMMIT();
    CPWAIT1();
    __syncthreads();
    STAGE_MMA64_LDSM(aA0, aB0);
    CPWAIT0();
    __syncthreads();
    STAGE_MMA64_LDSM(aA0 + bufo, aB0 + bufo);
    if (t < 128) {
        float s = 0.f;
#pragma unroll 16
        for (int k = 0; k < 64; ++k)
            s += rbs[k] * __half2float(BsT0[t][k]) + rbs[64 + k] * __half2float(BsT1[t][k]);
        rds[t] = s;
    }
    __syncthreads();
#pragma unroll
    for (int mi = 0; mi < 4; ++mi) {
        int r = m0 + moff + 16 * mi + grp;
#pragma unroll
        for (int ni = 0; ni < 4; ++ni) {
            int cl = noff + 8 * ni + 2 * tig;
            int c = n0 + cl;
            float r0 = rds[cl], r1 = rds[cl + 1];
            *(__half2*)&Cp[(size_t)r * P2 + c] = h2(acc[mi][ni][0] + r0, acc[mi][ni][1] + r1);
            *(__half2*)&Cp[(size_t)(r + 8) * P2 + c] = h2(acc[mi][ni][2] + r0, acc[mi][ni][3] + r1);
        }
    }
}

// ---------------- a = QK^T + 0.5*(rq + rk gathers), writes half (R12 exact) ----------------
__global__ void __launch_bounds__(256, 2) a_tc() {
    extern __shared__ __half sh[];
    int bh = blockIdx.z, b = bh >> 5, h = bh & 31;
    const __half* A  = g_qh + (size_t)b * Ss * HC + h * Cc;
    const __half* Bt = g_kh + (size_t)b * Ss * HC + h * Cc;
    const __half* rqb = g_rqh + (size_t)bh * (Ss * P2);
    const __half* rkb = g_rkh + (size_t)bh * (Ss * P2);
    __half* Cp = g_ah + (size_t)bh * (Ss * Ss);
    int m0 = blockIdx.y * 128, n0 = blockIdx.x * 128;
    int t = threadIdx.x, lane = t & 31, wid = t >> 5;
    int grp = lane >> 2, tig = lane & 3;
    int moff = (wid >> 2) * 64, noff = (wid & 3) * 32;
    int lrow = lane & 15, lcol = (lane >> 4) * 8;
    uint32_t aA0 = smem_u32(&((Tile)sh)[moff + lrow][lcol]);
    uint32_t aB0 = smem_u32(&((Tile)(sh + 2 * 128 * TW))[noff + lrow][lcol]);
    const uint32_t bufo = TILEB;
    float acc[4][4][4] = {};
    const __half* Ab = A + (size_t)m0 * HC;
    const __half* Bp = Bt + (size_t)n0 * HC;
    Tile AsT0 = (Tile)sh, AsT1 = (Tile)(sh + 128 * TW);
    Tile BsT0 = (Tile)(sh + 2 * 128 * TW), BsT1 = (Tile)(sh + 3 * 128 * TW);
    cp_tile64(AsT0, Ab, HC, t);
    cp_tile64(BsT0, Bp, HC, t);
    CPCOMMIT();
    cp_tile64(AsT1, Ab + 64, HC, t);
    cp_tile64(BsT1, Bp + 64, HC, t);
    CPCOMMIT();
    CPWAIT1();
    __syncthreads();
    STAGE_MMA64_LDSM(aA0, aB0);
    CPWAIT0();
    __syncthreads();
    STAGE_MMA64_LDSM(aA0 + bufo, aB0 + bufo);
#pragma unroll
    for (int mi = 0; mi < 4; ++mi) {
        int q0 = m0 + moff + 16 * mi + grp;
#pragma unroll
        for (int ni = 0; ni < 4; ++ni) {
            int kg = n0 + noff + 8 * ni + 2 * tig;
            float rq00 = __half2float(rqb[(size_t)q0 * P2 + kg - q0 + 512]);
            float rq01 = __half2float(rqb[(size_t)q0 * P2 + kg + 1 - q0 + 512]);
            float rq10 = __half2float(rqb[(size_t)(q0 + 8) * P2 + kg - q0 - 8 + 512]);
            float rq11 = __half2float(rqb[(size_t)(q0 + 8) * P2 + kg + 1 - q0 - 8 + 512]);
            float rk00 = __half2float(rkb[(size_t)kg * P2 + q0 - kg + 512]);
            float rk01 = __half2float(rkb[(size_t)(kg + 1) * P2 + q0 - kg - 1 + 512]);
            float rk10 = __half2float(rkb[(size_t)kg * P2 + q0 + 8 - kg + 512]);
            float rk11 = __half2float(rkb[(size_t)(kg + 1) * P2 + q0 + 7 - kg + 512]);
            *(__half2*)&Cp[(size_t)q0 * Ss + kg] =
                h2(acc[mi][ni][0] + 0.5f * (rq00 + rk00),
                   acc[mi][ni][1] + 0.5f * (rq01 + rk01));
            *(__half2*)&Cp[(size_t)(q0 + 8) * Ss + kg] =
                h2(acc[mi][ni][2] + 0.5f * (rq10 + rk10),
                   acc[mi][ni][3] + 0.5f * (rq11 + rk11));
        }
    }
}

// ---------------- final v2: block = (k-tile, q-chunk of 16, b)  (R12 exact) ----------------
__global__ void __launch_bounds__(256) final_tc2(const float* __restrict__ bpair,
                                                 float* __restrict__ out) {
    __shared__ __half At_s[2][128][34];
    __shared__ __half Ws[128][40];
    __shared__ float basef[2][128];
    int k0 = blockIdx.x * 128;
    int q0c = blockIdx.y * 16;
    int b = blockIdx.z;
    int t = threadIdx.x, lane = t & 31, wid = t >> 5;
    int grp = lane >> 2, tig = lane & 3;
    int moff = (wid >> 2) * 64, noff = (wid & 3) * 32;
#pragma unroll
    for (int i = 0; i < 2; ++i) {
        int c = t + 256 * i;
        int r = c >> 2, c16 = (c & 3) * 8;
        cpa16(&Ws[r][c16], g_wpt + (size_t)r * 32 + c16);
    }
    CPCOMMIT();
    float bpr = (t < 128) ? bpair[t] : 0.f;
    float2 ykr[4][4][2];
#pragma unroll
    for (int mi = 0; mi < 4; ++mi) {
        int kl0 = moff + 16 * mi + grp;
#pragma unroll
        for (int ni = 0; ni < 4; ++ni) {
            int f = noff + 8 * ni + 2 * tig;
            ykr[mi][ni][0] = *(const float2*)&g_yk[((size_t)(b * 512 + k0 + kl0)) * 128 + f];
            ykr[mi][ni][1] = *(const float2*)&g_yk[((size_t)(b * 512 + k0 + kl0 + 8)) * 128 + f];
        }
    }
    if (t < 128) basef[0][t] = bpr + g_yq[((size_t)(b * 512 + q0c)) * 128 + t];
#pragma unroll
    for (int it = 0; it < 8; ++it) {
        int id = t + 256 * it;
        int hh = id >> 6, j = id & 63;
        __half2 v = *(const __half2*)&g_ah[(((size_t)(b * 32 + hh) * Ss + q0c) * Ss) + k0 + 2 * j];
        At_s[0][2 * j][hh] = __low2half(v);
        At_s[0][2 * j + 1][hh] = __high2half(v);
    }
    CPWAIT0();
    for (int qi = 0; qi < 16; ++qi) {
        int cur = qi & 1, nxt = cur ^ 1;
        __syncthreads();
        if (qi < 15) {
            int qn = q0c + qi + 1;
            if (t < 128) basef[nxt][t] = bpr + g_yq[((size_t)(b * 512 + qn)) * 128 + t];
#pragma unroll
            for (int it = 0; it < 8; ++it) {
                int id = t + 256 * it;
                int hh = id >> 6, j = id & 63;
                __half2 v = *(const __half2*)&g_ah[(((size_t)(b * 32 + hh) * Ss + qn) * Ss) + k0 + 2 * j];
                At_s[nxt][2 * j][hh] = __low2half(v);
                At_s[nxt][2 * j + 1][hh] = __high2half(v);
            }
        }
        float acc[4][4][4] = {};
#pragma unroll
        for (int ks = 0; ks < 2; ++ks) {
            int koff = ks * 16 + 2 * tig;
            uint32_t af[4][4], bf[4][2];
#pragma unroll
            for (int mi = 0; mi < 4; ++mi) {
                int r = moff + 16 * mi + grp;
                af[mi][0] = *(const uint32_t*)&At_s[cur][r][koff];
                af[mi][1] = *(const uint32_t*)&At_s[cur][r + 8][koff];
                af[mi][2] = *(const uint32_t*)&At_s[cur][r][koff + 8];
                af[mi][3] = *(const uint32_t*)&At_s[cur][r + 8][koff + 8];
            }
#pragma unroll
            for (int ni = 0; ni < 4; ++ni) {
                int c = noff + 8 * ni + grp;
                bf[ni][0] = *(const uint32_t*)&Ws[c][koff];
                bf[ni][1] = *(const uint32_t*)&Ws[c][koff + 8];
            }
#pragma unroll
            for (int mi = 0; mi < 4; ++mi)
#pragma unroll
                for (int ni = 0; ni < 4; ++ni) MMA_F16(acc[mi][ni], af[mi], bf[ni]);
        }
        int q = q0c + qi;
        size_t rb = ((size_t)(b * 512 + q) * 512 + k0);
#pragma unroll
        for (int mi = 0; mi < 4; ++mi) {
            int kl0 = moff + 16 * mi + grp;
            size_t row0 = (rb + kl0) * 128, row1 = row0 + (size_t)8 * 128;
#pragma unroll
            for (int ni = 0; ni < 4; ++ni) {
                int f = noff + 8 * ni + 2 * tig;
                float b0 = basef[cur][f], b1 = basef[cur][f + 1];
                *(float2*)&out[row0 + f] = make_float2(acc[mi][ni][0] + b0 + ykr[mi][ni][0].x,
                                                       acc[mi][ni][1] + b1 + ykr[mi][ni][0].y);
                *(float2*)&out[row1 + f] = make_float2(acc[mi][ni][2] + b0 + ykr[mi][ni][1].x,
                                                       acc[mi][ni][3] + b1 + ykr[mi][ni][1].y);
            }
        }
    }
}

// ---------------- launcher (R12 schedule exact) ----------------
extern "C" void kernel_launch(void* const* d_in, const int* in_sizes, int n_in,
                              void* d_out, int out_size) {
    const float* x        = (const float*)d_in[0];
    const float* scale    = (const float*)d_in[1];
    const float* w_q      = (const float*)d_in[2];
    const float* w_k      = (const float*)d_in[3];
    const float* w_pos    = (const float*)d_in[4];
    const float* b_pos    = (const float*)d_in[5];
    const float* q_r_bias = (const float*)d_in[6];
    const float* k_r_bias = (const float*)d_in[7];
    const float* w_yq     = (const float*)d_in[8];
    const float* w_yk     = (const float*)d_in[9];
    const float* w_pair   = (const float*)d_in[10];
    const float* b_pair   = (const float*)d_in[11];
    float* out = (float*)d_out;

    __half *p_wqt, *p_wkt, *p_wyqt, *p_wykt, *p_wpt;
    cudaGetSymbolAddress((void**)&p_wqt, g_wqt);
    cudaGetSymbolAddress((void**)&p_wkt, g_wkt);
    cudaGetSymbolAddress((void**)&p_wyqt, g_wyqt);
    cudaGetSymbolAddress((void**)&p_wykt, g_wykt);
    cudaGetSymbolAddress((void**)&p_wpt, g_wpt);

    cudaFuncSetAttribute(proj_tc, cudaFuncAttributeMaxDynamicSharedMemorySize, SMEMB);
    cudaFuncSetAttribute(ygemm_tc, cudaFuncAttributeMaxDynamicSharedMemorySize, SMEMB);
    cudaFuncSetAttribute(rel_tc, cudaFuncAttributeMaxDynamicSharedMemorySize, SMEMB);
    cudaFuncSetAttribute(a_tc, cudaFuncAttributeMaxDynamicSharedMemorySize, SMEMB);

    transpose_qk2<<<dim3(128, 48, 2), dim3(32, 8)>>>(w_q, w_k, p_wqt, p_wkt, Dd, HC); // 1
    pool_norm_kernel<<<1024, 384>>>(x, scale);                                        // 2
    init_kernel<<<9, 544>>>(w_pos);                                                   // 3
    proj_tc<<<dim3(32, 8, 2), 256, SMEMB>>>();                                        // 4 (profiled)
    posenc_kernel<<<dim3(1024, 4), 256>>>(b_pos);                                     // 5
    transpose_qk2<<<dim3(4, 48, 2), dim3(32, 8)>>>(w_yq, w_yk, p_wyqt, p_wykt, Dd, PAIRF); // 6
    transpose_h<<<dim3(4, 1), dim3(32, 8)>>>(w_pair, p_wpt, Hh, PAIRF);               // 7
    ygemm_tc<<<dim3(1, 8, 16), 256, SMEMB>>>();                                       // 8
    reduce_y_kernel<<<512, 256>>>();                                                  // 9
    rel_tc<<<dim3(5, 4, 128), 256, SMEMB>>>(q_r_bias, k_r_bias);                      // 10
    a_tc<<<dim3(4, 4, 64), 256, SMEMB>>>();                                           // 11
    final_tc2<<<dim3(4, 32, 2), 256>>>(b_pair, out);                                  // 12
}